// round 8
// baseline (speedup 1.0000x reference)
#include <cuda_runtime.h>
#include <math.h>

#define NC 40
#define NB 256                    // histogram bins over x in [-12,12]
#define NWD (NB/2)                // packed u32 words per class-label = 128
#define NCL (NC*2)                // class-label pairs = 80
#define WORDS (NCL*NWD)           // 10240 packed words
#define G1 145                    // pass1 grid: 1 block/SM, %5==0 (fixed-class trick)
#define T1 1024                   // pass1 block size
#define G3 1180                   // pass3 grid (%5==0)
#define BANDX 1.3862944f          // ln(4): g>=0.8 boundary in |x| (mismatch side)
#define BSC (256.0f/24.0f)        // x -> bin scale

// ---------------- scratch (device globals) -----------------------------------
__device__ float    g_loss_sum[NC];
__device__ unsigned g_pos_sum[NC];
__device__ unsigned g_hist[WORDS];       // packed 16-bit halves; max count/bin ~1.2K << 65536
__device__ double   g_acc;
__device__ unsigned g_done;

// per-class packed params
__device__ float g_c_w1[NC];     // weight if t==1 (pre-drop)
__device__ float g_c_w0[NC];     // weight if t==0 (pre-drop)
__device__ float g_c_drate[NC];
__device__ float g_c_keep[NC];   // keep fraction for boundary bin
__device__ int   g_c_m1[NC];     // threshold bin when majority label==1 (else -1)
__device__ int   g_c_m0[NC];     // threshold bin when majority label==0 (else -1)
__device__ int   g_c_need[NC];
__device__ int   g_c_majpos[NC];
__device__ int   g_c_k[NC];

// L2 evict_last policy + cache_hint loads: keep the 63MB working set in L2
__device__ __forceinline__ unsigned long long mkpol() {
    unsigned long long pol;
    asm("createpolicy.fractional.L2::evict_last.b64 %0, 1.0;" : "=l"(pol));
    return pol;
}
__device__ __forceinline__ float4 ldg_el(const float4* p, unsigned long long pol) {
    float4 v;
    asm volatile("ld.global.nc.L2::cache_hint.v4.f32 {%0,%1,%2,%3}, [%4], %5;"
                 : "=f"(v.x), "=f"(v.y), "=f"(v.z), "=f"(v.w)
                 : "l"(p), "l"(pol));
    return v;
}

// ---------------- kernels -----------------------------------------------------
__global__ void k_zero() {
    int i = blockIdx.x * 256 + threadIdx.x;
    if (i < WORDS) g_hist[i] = 0u;
    if (i < NC) { g_loss_sum[i] = 0.0f; g_pos_sum[i] = 0u; }
    if (i == 0) { g_acc = 0.0; g_done = 0u; }
}

// fused pass1: per-class sum(bce), count(t==1), per-label x-bin histogram
// privatized in smem (16-bit packed); flushed with spread global atomics.
__global__ __launch_bounds__(T1) void k_pass1(const float4* __restrict__ pred,
                                              const float4* __restrict__ targ,
                                              int n4) {
    __shared__ unsigned s_h[WORDS];          // 40 KB
    __shared__ float    s_loss[NC];
    __shared__ unsigned s_pos[NC];
    int tid = threadIdx.x;
    for (int i = tid; i < WORDS; i += T1) s_h[i] = 0u;
    if (tid < NC) { s_loss[tid] = 0.0f; s_pos[tid] = 0u; }
    __syncthreads();

    unsigned long long pol = mkpol();
    int gt = blockIdx.x * T1 + tid;
    int stride = G1 * T1;
    int c0 = (gt * 4) % NC;                  // fixed per thread (stride*4 % 40 == 0)

    float    l[4] = {0.f, 0.f, 0.f, 0.f};
    unsigned p[4] = {0u, 0u, 0u, 0u};
    for (int i = gt; i < n4; i += stride) {
        float4 x = ldg_el(pred + i, pol);
        float4 t = ldg_el(targ + i, pol);
        float xs[4] = {x.x, x.y, x.z, x.w};
        float ts[4] = {t.x, t.y, t.z, t.w};
#pragma unroll
        for (int j = 0; j < 4; j++) {
            float xv = xs[j];
            int   t1 = (ts[j] != 0.0f) ? 1 : 0;
            float ax = fabsf(xv);
            float L  = __logf(1.0f + __expf(-ax));
            bool mism = (xv >= 0.0f) != (t1 != 0);
            l[j] += mism ? (L + ax) : L;
            p[j] += (unsigned)t1;
            int b = (int)fmaf(xv, BSC, 128.0f);
            b = min(max(b, 0), NB - 1);
            int w = ((c0 + j) * 2 + t1) * NWD + (b >> 1);
            atomicAdd(&s_h[w], 1u << ((b & 1) << 4));
        }
    }
#pragma unroll
    for (int j = 0; j < 4; j++) {
        atomicAdd(&s_loss[c0 + j], l[j]);
        atomicAdd(&s_pos[c0 + j], p[j]);
    }
    __syncthreads();
    // flush: packed-word global atomics (halves can't carry; global max/bin ~1.2K)
    for (int i = tid; i < WORDS; i += T1) {
        unsigned v = s_h[i];
        if (v) atomicAdd(&g_hist[i], v);
    }
    if (tid < NC) {
        atomicAdd(&g_loss_sum[tid], s_loss[tid]);
        atomicAdd(&g_pos_sum[tid], s_pos[tid]);
    }
}

// fused pass2: per-class params, then g-ordered cumulative scan. 1 block.
__global__ __launch_bounds__(256) void k_pass2(const float* __restrict__ hard_rand,
                                               const float* __restrict__ pos_prop,
                                               float Bf) {
    __shared__ float s_ln[NC];
    int tid = threadIdx.x;
    if (tid < NC) s_ln[tid] = log10f(1.0f + g_loss_sum[tid]);
    __syncthreads();

    // ---- phase A: per-class params (threads 0..NC-1) ----
    if (tid < NC) {
        int c = tid;
        float mn = s_ln[0], mx = s_ln[0];
#pragma unroll
        for (int j = 1; j < NC; j++) { mn = fminf(mn, s_ln[j]); mx = fmaxf(mx, s_ln[j]); }

        float norm  = 5.0f - 10.0f * (s_ln[c] - mn) / (mx - mn);
        float drate = 1.0f / (1.0f + expf(-norm));

        float pos = (float)g_pos_sum[c];
        float neg = Bf - pos;
        float bal_pos = pos_prop[c] * Bf;
        float bal_neg = Bf - bal_pos;
        bool pos_gt = pos > bal_pos;
        bool neg_gt = neg > bal_neg;

        float balance = pos_gt ? bal_pos : (neg_gt ? bal_neg : 0.0f);
        float dnf     = pos_gt ? (pos - bal_pos) : (neg_gt ? (neg - bal_neg) : 0.0f);
        int   k       = (int)floorf(dnf);

        bool  hard    = hard_rand[c] > drate;
        float maj_lab = pos_gt ? 1.0f : 0.0f;
        float min_lab = neg_gt ? 1.0f : 0.0f;
        float maj_cnt = (maj_lab == 1.0f) ? pos : neg;
        float min_cnt = (min_lab == 1.0f) ? pos : neg;

        float w_maj    = balance / fmaxf(maj_cnt, 1.0f);
        float wmin_eff = (min_cnt > 0.0f) ? (Bf - balance) / fmaxf(min_cnt, 1.0f) : 1.0f;

        int majpos = (maj_lab == 1.0f) ? 1 : 0;
        bool need = (!hard) && (k > 0);

        g_c_w1[c]     = hard ? (majpos ? w_maj : 1.0f) : ((min_lab == 1.0f) ? wmin_eff : 1.0f);
        g_c_w0[c]     = hard ? (majpos ? 1.0f : w_maj) : ((min_lab == 1.0f) ? 1.0f : wmin_eff);
        g_c_drate[c]  = drate;
        g_c_keep[c]   = 1.0f;
        g_c_m1[c]     = -1;
        g_c_m0[c]     = -1;
        g_c_need[c]   = need ? 1 : 0;
        g_c_majpos[c] = majpos;
        g_c_k[c]      = k;
    }
    __syncthreads();

    // ---- phase B: warp-per-class scan over packed histogram ----
    int warp = tid >> 5;
    int lane = tid & 31;
    for (int c = warp; c < NC; c += 8) {
        if (!g_c_need[c]) continue;
        int k  = g_c_k[c];
        int mp = g_c_majpos[c];
        const unsigned* hp = &g_hist[(c * 2 + mp) * NWD];
        int v[8];
        int sum = 0;
#pragma unroll
        for (int j = 0; j < 8; j++) {
            int gi  = lane * 8 + j;                    // g-ascending index
            int bin = mp ? (NB - 1 - gi) : gi;         // majority=1 -> g desc in x
            unsigned wv = hp[bin >> 1];
            v[j] = (int)((bin & 1) ? (wv >> 16) : (wv & 0xffffu));
            sum += v[j];
        }
        int incl = sum;
#pragma unroll
        for (int o = 1; o < 32; o <<= 1) {
            int u = __shfl_up_sync(0xffffffffu, incl, o);
            if (lane >= o) incl += u;
        }
        unsigned ball = __ballot_sync(0xffffffffu, incl >= k);
        int sel = __ffs(ball) - 1;
        if (lane == sel) {
            int cum = incl - sum;
            int m = -1;
            float keep = 1.0f;
#pragma unroll
            for (int j = 0; j < 8; j++) {
                int cb = v[j];
                if (m < 0 && cum + cb >= k) {
                    int gi = lane * 8 + j;
                    m = mp ? (NB - 1 - gi) : gi;
                    keep = 1.0f - (float)(k - cum) / (float)cb;
                }
                cum += cb;
            }
            g_c_keep[c] = keep;
            if (mp) g_c_m1[c] = m; else g_c_m0[c] = m;
        }
    }
}

// per-4-element weighted-bce body (shared by unrolled copies)
__device__ __forceinline__ float body4(float4 x, float4 t, float4 r,
                                       const float* w1, const float* w0,
                                       const float* dr, const float* kp,
                                       const int* m1, const int* m0) {
    float xs[4] = {x.x, x.y, x.z, x.w};
    float ts[4] = {t.x, t.y, t.z, t.w};
    float rs[4] = {r.x, r.y, r.z, r.w};
    float acc = 0.0f;
#pragma unroll
    for (int j = 0; j < 4; j++) {
        float xv = xs[j];
        bool  t1 = ts[j] != 0.0f;
        float ax = fabsf(xv);
        float L  = __logf(1.0f + __expf(-ax));
        bool mism = (xv >= 0.0f) != t1;
        float bce = mism ? (L + ax) : L;

        int b = (int)fmaf(xv, BSC, 128.0f);
        b = min(max(b, 0), NB - 1);

        float w = t1 ? w1[j] : w0[j];
        int   m = t1 ? m1[j] : m0[j];
        if (m >= 0) {
            bool drop = t1 ? (b > m) : (b < m);
            if (drop)        w = 0.0f;
            else if (b == m) w *= kp[j];
        }
        if (mism && ax >= BANDX && rs[j] > dr[j]) w = 0.0f;
        acc = fmaf(bce, w, acc);
    }
    return acc;
}

// pass3: weighted sum + fused finalize (last block writes out)
__global__ __launch_bounds__(256) void k_pass3(const float4* __restrict__ pred,
                                               const float4* __restrict__ targ,
                                               const float4* __restrict__ rm,
                                               float* __restrict__ out,
                                               int n4, int n) {
    int tid = threadIdx.x;
    int gt = blockIdx.x * 256 + tid;
    const int stride = G3 * 256;
    int c0 = (gt * 4) % NC;

    float w1[4], w0[4], dr[4], kp[4];
    int m1[4], m0[4];
#pragma unroll
    for (int j = 0; j < 4; j++) {
        int c = c0 + j;
        w1[j] = g_c_w1[c];  w0[j] = g_c_w0[c];
        dr[j] = g_c_drate[c]; kp[j] = g_c_keep[c];
        m1[j] = g_c_m1[c];  m0[j] = g_c_m0[c];
    }

    unsigned long long pol = mkpol();
    float acc0 = 0.0f, acc1 = 0.0f;
    int i = gt;
    // unrolled x2: two independent load triples in flight
    for (; i + stride < n4; i += 2 * stride) {
        float4 xa = ldg_el(pred + i, pol);
        float4 ta = ldg_el(targ + i, pol);
        float4 ra = ldg_el(rm + i, pol);
        float4 xb = ldg_el(pred + i + stride, pol);
        float4 tb = ldg_el(targ + i + stride, pol);
        float4 rb = ldg_el(rm + i + stride, pol);
        acc0 += body4(xa, ta, ra, w1, w0, dr, kp, m1, m0);
        acc1 += body4(xb, tb, rb, w1, w0, dr, kp, m1, m0);
    }
    for (; i < n4; i += stride) {
        float4 x = ldg_el(pred + i, pol);
        float4 t = ldg_el(targ + i, pol);
        float4 r = ldg_el(rm + i, pol);
        acc0 += body4(x, t, r, w1, w0, dr, kp, m1, m0);
    }
    float local = acc0 + acc1;

    // warp reduce -> block reduce -> double atomic -> last block finalizes
#pragma unroll
    for (int o = 16; o > 0; o >>= 1)
        local += __shfl_down_sync(0xffffffffu, local, o);
    __shared__ float s_red[8];
    int wid = tid >> 5, lane = tid & 31;
    if (lane == 0) s_red[wid] = local;
    __syncthreads();
    if (wid == 0) {
        float v = (lane < 8) ? s_red[lane] : 0.0f;
#pragma unroll
        for (int o = 4; o > 0; o >>= 1)
            v += __shfl_down_sync(0xffffffffu, v, o);
        if (lane == 0) {
            atomicAdd(&g_acc, (double)v);
            __threadfence();
            unsigned old = atomicAdd(&g_done, 1u);
            if (old == G3 - 1) {
                double total = atomicAdd(&g_acc, 0.0);   // coherent read
                out[0] = (float)(total / (double)n);
            }
        }
    }
}

// ---------------- launch ------------------------------------------------------
extern "C" void kernel_launch(void* const* d_in, const int* in_sizes, int n_in,
                              void* d_out, int out_size) {
    const float4* pred     = (const float4*)d_in[0];
    const float4* targ     = (const float4*)d_in[1];
    const float4* rm       = (const float4*)d_in[2];
    const float*  hard_rnd = (const float*)d_in[3];
    const float*  pos_prop = (const float*)d_in[4];
    float* out = (float*)d_out;

    int n  = in_sizes[0];           // B*C (divisible by 4)
    int n4 = n / 4;
    float Bf = (float)(n / NC);

    k_zero<<<(WORDS + 255) / 256, 256>>>();
    k_pass1<<<G1, T1>>>(pred, targ, n4);
    k_pass2<<<1, 256>>>(hard_rnd, pos_prop, Bf);
    k_pass3<<<G3, 256>>>(pred, targ, rm, out, n4, n);
}